// round 8
// baseline (speedup 1.0000x reference)
#include <cuda_runtime.h>
#include <cuda_bf16.h>
#include <cstdint>

#define BATCH 4096
#define DIM   512
#define N2    (2 * BATCH)   // 8192
#define INV_T 10.0f

#define MT  32              // row tiles of 256 (8192/256)
#define NT  64              // col tiles of 128
#define NTILES 1056         // sum_{TM=0}^{31} (64 - 2*TM)

// ---------------- device scratch (no allocation allowed) ----------------
__device__ __nv_bfloat16 g_reps[(size_t)N2 * DIM];  // normalized rows, bf16
__device__ float g_pos[BATCH];                      // dot(z_i, z_j) fp32
__device__ float g_denom[N2];                       // masked row sums of exp(sim/T)

// ---------------- helpers ----------------
static __device__ __forceinline__ uint32_t smem_u32(const void* p) {
    uint32_t a;
    asm("{ .reg .u64 t; cvta.to.shared.u64 t, %1; cvt.u32.u64 %0, t; }"
        : "=r"(a) : "l"(p));
    return a;
}

static __device__ __forceinline__ uint32_t sw128(uint32_t o) {
    return o ^ ((o >> 3) & 0x70u);   // SW128 swizzle for 128B rows
}

static __device__ __forceinline__ void ldsm4(uint32_t* r, uint32_t addr) {
    asm volatile("ldmatrix.sync.aligned.m8n8.x4.shared.b16 {%0,%1,%2,%3}, [%4];"
                 : "=r"(r[0]), "=r"(r[1]), "=r"(r[2]), "=r"(r[3]) : "r"(addr));
}

static __device__ __forceinline__ void mma16816(float* c, const uint32_t* a,
                                                uint32_t b0, uint32_t b1) {
    asm volatile(
        "mma.sync.aligned.m16n8k16.row.col.f32.bf16.bf16.f32 "
        "{%0,%1,%2,%3}, {%4,%5,%6,%7}, {%8,%9}, {%0,%1,%2,%3};"
        : "+f"(c[0]), "+f"(c[1]), "+f"(c[2]), "+f"(c[3])
        : "r"(a[0]), "r"(a[1]), "r"(a[2]), "r"(a[3]), "r"(b0), "r"(b1));
}

static __device__ __forceinline__ void cp_async16(uint32_t dst, const void* src) {
    asm volatile("cp.async.cg.shared.global [%0], [%1], 16;"
                 :: "r"(dst), "l"(src) : "memory");
}

// ---------------- kernel 1: normalize + positives + zero denom ----------------
// 2048 blocks x 256 threads; each half-block (128 threads) handles one row pair k.
__global__ void __launch_bounds__(256) prep_kernel(
    const float* __restrict__ ei, const float* __restrict__ ej)
{
    const int tid  = threadIdx.x;
    const int half = tid >> 7;          // 0 or 1
    const int t    = tid & 127;         // 0..127, 4 floats each
    const int k    = blockIdx.x * 2 + half;

    if (tid < 4) g_denom[blockIdx.x * 4 + tid] = 0.0f;

    const float4 a = *reinterpret_cast<const float4*>(ei + (size_t)k * DIM + t * 4);
    const float4 b = *reinterpret_cast<const float4*>(ej + (size_t)k * DIM + t * 4);

    float ni = a.x*a.x + a.y*a.y + a.z*a.z + a.w*a.w;
    float nj = b.x*b.x + b.y*b.y + b.z*b.z + b.w*b.w;
    float dd = a.x*b.x + a.y*b.y + a.z*b.z + a.w*b.w;
    #pragma unroll
    for (int o = 16; o; o >>= 1) {
        ni += __shfl_xor_sync(0xffffffffu, ni, o);
        nj += __shfl_xor_sync(0xffffffffu, nj, o);
        dd += __shfl_xor_sync(0xffffffffu, dd, o);
    }
    __shared__ float sni[2][4], snj[2][4], sdd[2][4];
    const int w2 = (tid >> 5) & 3;      // warp index within half
    if ((tid & 31) == 0) { sni[half][w2] = ni; snj[half][w2] = nj; sdd[half][w2] = dd; }
    __syncthreads();
    const float NI = sni[half][0] + sni[half][1] + sni[half][2] + sni[half][3];
    const float NJ = snj[half][0] + snj[half][1] + snj[half][2] + snj[half][3];
    const float DD = sdd[half][0] + sdd[half][1] + sdd[half][2] + sdd[half][3];

    const float rin = 1.0f / fmaxf(sqrtf(NI), 1e-12f);
    const float rjn = 1.0f / fmaxf(sqrtf(NJ), 1e-12f);

    __nv_bfloat162 ia = __floats2bfloat162_rn(a.x * rin, a.y * rin);
    __nv_bfloat162 ib = __floats2bfloat162_rn(a.z * rin, a.w * rin);
    __nv_bfloat162 ja = __floats2bfloat162_rn(b.x * rjn, b.y * rjn);
    __nv_bfloat162 jb = __floats2bfloat162_rn(b.z * rjn, b.w * rjn);
    uint2 iv, jv;
    iv.x = *reinterpret_cast<uint32_t*>(&ia); iv.y = *reinterpret_cast<uint32_t*>(&ib);
    jv.x = *reinterpret_cast<uint32_t*>(&ja); jv.y = *reinterpret_cast<uint32_t*>(&jb);
    *reinterpret_cast<uint2*>(g_reps + (size_t)k * DIM + t * 4) = iv;
    *reinterpret_cast<uint2*>(g_reps + (size_t)(BATCH + k) * DIM + t * 4) = jv;
    if (t == 0) g_pos[k] = DD * rin * rjn;
}

// ---------------- kernel 2: symmetric tiled HMMA GEMM + fused exp sums ----------------
// 256x128 tiles of sim = R R^T, enumerated over {(TM,TN): TN in [2*TM, 63]}.
// 256 threads = 8 warps in 4(M) x 2(N); warp tile 64x64. BK=64, 3-stage cp.async,
// SW128 smem, m16n8k16 bf16 HMMA. Epilogue: strictly-upper mask, exp(10*s),
// row sums -> denom[row], col sums -> denom[col].
#define GT 256
#define STG 3
#define A_BYTES 32768            // 256 rows x 64 cols bf16
#define B_BYTES 16384            // 128 rows x 64 cols bf16
#define STAGE_BYTES (A_BYTES + B_BYTES)
#define SMEM_BYTES  (STG * STAGE_BYTES + 1024)

__global__ void __launch_bounds__(GT, 1) simexp_kernel()
{
    extern __shared__ char dynsmem[];
    const uint32_t base = (smem_u32(dynsmem) + 1023u) & ~1023u;

    const int tid  = threadIdx.x;
    const int wid  = tid >> 5;
    const int lane = tid & 31;
    const int warp_m = (wid & 3) * 64;   // 4 warps over M (256)
    const int warp_n = (wid >> 2) * 64;  // 2 warps over N (128)

    // decode bid -> (TM, TN), TN in [2*TM, 63]; C(TM) = 64*TM - TM*(TM-1)
    const int bid = blockIdx.x;
    int TM = 0, C = 0;
    while (C + (NT - 2 * TM) <= bid) { C += NT - 2 * TM; ++TM; }
    const int TN = 2 * TM + (bid - C);
    const bool interior = (TN >= 2 * TM + 2);   // entire tile strictly above diagonal

    const __nv_bfloat16* Abase = g_reps + (size_t)TM * 256 * DIM;
    const __nv_bfloat16* Bbase = g_reps + (size_t)TN * 128 * DIM;

    // ---- async load of K-chunk c into stage s ----
    auto load_stage = [&](int s, int c) {
        const uint32_t As = base + (uint32_t)s * STAGE_BYTES;
        const uint32_t Bs = As + A_BYTES;
        #pragma unroll
        for (int it = 0; it < 8; ++it) {            // A: 256 rows x 8 chunks
            const int id  = tid + it * GT;           // 0..2047
            const int row = id >> 3, kc = id & 7;
            cp_async16(As + sw128((uint32_t)(row * 128 + kc * 16)),
                       Abase + (size_t)row * DIM + c * 64 + kc * 8);
        }
        #pragma unroll
        for (int it = 0; it < 4; ++it) {            // B: 128 rows x 8 chunks
            const int id  = tid + it * GT;           // 0..1023
            const int row = id >> 3, kc = id & 7;
            cp_async16(Bs + sw128((uint32_t)(row * 128 + kc * 16)),
                       Bbase + (size_t)row * DIM + c * 64 + kc * 8);
        }
    };

    float acc[4][8][4];
    #pragma unroll
    for (int mi = 0; mi < 4; ++mi)
        #pragma unroll
        for (int ni = 0; ni < 8; ++ni)
            #pragma unroll
            for (int e = 0; e < 4; ++e) acc[mi][ni][e] = 0.f;

    load_stage(0, 0);
    asm volatile("cp.async.commit_group;" ::: "memory");
    load_stage(1, 1);
    asm volatile("cp.async.commit_group;" ::: "memory");

    for (int c = 0; c < 8; ++c) {
        asm volatile("cp.async.wait_group 1;" ::: "memory");
        __syncthreads();

        if (c + 2 < 8) load_stage((c + 2) % STG, c + 2);
        asm volatile("cp.async.commit_group;" ::: "memory");

        const uint32_t As = base + (uint32_t)((c % STG) * STAGE_BYTES);
        const uint32_t Bs = As + A_BYTES;

        #pragma unroll
        for (int ks = 0; ks < 4; ++ks) {   // 4 x k16 within BK=64
            uint32_t af[4][4], bf[4][4];
            #pragma unroll
            for (int mi = 0; mi < 4; ++mi) {
                const int row = warp_m + mi * 16 + (lane & 15);
                ldsm4(af[mi], As + sw128((uint32_t)(row * 128 + ks * 32 + (lane >> 4) * 16)));
            }
            #pragma unroll
            for (int p = 0; p < 4; ++p) {
                const int row = warp_n + p * 16 + (lane & 7) + ((lane >> 4) & 1) * 8;
                ldsm4(bf[p], Bs + sw128((uint32_t)(row * 128 + ks * 32 + ((lane >> 3) & 1) * 16)));
            }
            #pragma unroll
            for (int mi = 0; mi < 4; ++mi)
                #pragma unroll
                for (int ni = 0; ni < 8; ++ni)
                    mma16816(acc[mi][ni], af[mi],
                             bf[ni >> 1][(ni & 1) * 2], bf[ni >> 1][(ni & 1) * 2 + 1]);
        }
    }

    // ---- fused epilogue: strictly-upper contributions ----
    // C-frag map: c[2h+e] = (row = lane/4 + 8h, col = 2*(lane%4) + e)
    const int growb = TM * 256 + warp_m + (lane >> 2);
    const int gcolb = TN * 128 + warp_n + 2 * (lane & 3);

    float rsum[8];                       // [mi*2 + h]
    float csum[8][2];                    // [ni][e]
    #pragma unroll
    for (int i = 0; i < 8; ++i) { rsum[i] = 0.f; csum[i][0] = 0.f; csum[i][1] = 0.f; }

    #pragma unroll
    for (int mi = 0; mi < 4; ++mi)
        #pragma unroll
        for (int ni = 0; ni < 8; ++ni)
            #pragma unroll
            for (int h = 0; h < 2; ++h)
                #pragma unroll
                for (int e = 0; e < 2; ++e) {
                    const int grow = growb + mi * 16 + h * 8;
                    const int gcol = gcolb + ni * 8 + e;
                    float v = __expf(acc[mi][ni][2 * h + e] * INV_T);
                    if (!interior && grow >= gcol) v = 0.f;  // keep strictly upper
                    rsum[mi * 2 + h] += v;
                    csum[ni][e] += v;
                }

    // row sums: reduce over lanes sharing a row (lane bits 0,1)
    #pragma unroll
    for (int i = 0; i < 8; ++i) {
        rsum[i] += __shfl_xor_sync(0xffffffffu, rsum[i], 1);
        rsum[i] += __shfl_xor_sync(0xffffffffu, rsum[i], 2);
    }
    if ((lane & 3) == 0) {
        #pragma unroll
        for (int mi = 0; mi < 4; ++mi)
            #pragma unroll
            for (int h = 0; h < 2; ++h)
                atomicAdd(&g_denom[growb + mi * 16 + h * 8], rsum[mi * 2 + h]);
    }

    // col sums: reduce over lanes sharing a column (lane bits 2,3,4)
    #pragma unroll
    for (int ni = 0; ni < 8; ++ni)
        #pragma unroll
        for (int e = 0; e < 2; ++e) {
            float v = csum[ni][e];
            v += __shfl_xor_sync(0xffffffffu, v, 4);
            v += __shfl_xor_sync(0xffffffffu, v, 8);
            v += __shfl_xor_sync(0xffffffffu, v, 16);
            if ((lane >> 2) == 0)
                atomicAdd(&g_denom[gcolb + ni * 8 + e], v);
        }
}

// ---------------- kernel 3: final reduction ----------------
__global__ void __launch_bounds__(1024) finish_kernel(float* out, int out_size)
{
    const int tid = threadIdx.x;
    float sl = 0.f, sp = 0.f;
    for (int r = tid; r < N2; r += 1024) sl += logf(g_denom[r]);
    for (int k = tid; k < BATCH; k += 1024) sp += g_pos[k];

    #pragma unroll
    for (int o = 16; o; o >>= 1) {
        sl += __shfl_xor_sync(0xffffffffu, sl, o);
        sp += __shfl_xor_sync(0xffffffffu, sp, o);
    }
    __shared__ float rl[32], rp[32];
    const int wid = tid >> 5, lid = tid & 31;
    if (lid == 0) { rl[wid] = sl; rp[wid] = sp; }
    __syncthreads();
    if (wid == 0) {
        float x = rl[lid];
        float y = rp[lid];
        #pragma unroll
        for (int o = 16; o; o >>= 1) {
            x += __shfl_xor_sync(0xffffffffu, x, o);
            y += __shfl_xor_sync(0xffffffffu, y, o);
        }
        if (lid == 0) {
            const float loss = (x - 2.0f * y * INV_T) / (float)N2;
            for (int i = 0; i < out_size; ++i) out[i] = loss;
        }
    }
}

// ---------------- launch ----------------
extern "C" void kernel_launch(void* const* d_in, const int* in_sizes, int n_in,
                              void* d_out, int out_size)
{
    (void)in_sizes; (void)n_in;
    const float* ei = (const float*)d_in[0];
    const float* ej = (const float*)d_in[1];

    cudaFuncSetAttribute(simexp_kernel,
                         cudaFuncAttributeMaxDynamicSharedMemorySize, SMEM_BYTES);

    prep_kernel<<<N2 / 4, 256>>>(ei, ej);
    simexp_kernel<<<NTILES, GT, SMEM_BYTES>>>();
    finish_kernel<<<1, 1024>>>((float*)d_out, out_size);
}

// round 10
// speedup vs baseline: 1.0039x; 1.0039x over previous
#include <cuda_runtime.h>
#include <cuda_bf16.h>
#include <cstdint>

#define BATCH 4096
#define DIM   512
#define N2    (2 * BATCH)   // 8192
#define INV_T 10.0f

#define MT  32              // row tiles of 256 (8192/256)
#define NT  64              // col tiles of 128
#define NTILES 1056         // sum_{TM=0}^{31} (64 - 2*TM)

// ---------------- device scratch (no allocation allowed) ----------------
__device__ __nv_bfloat16 g_reps[(size_t)N2 * DIM];  // normalized rows, bf16
__device__ float g_pos[BATCH];                      // dot(z_i, z_j) fp32
__device__ float g_denom[N2];                       // masked row sums of exp(sim/T)

// ---------------- helpers ----------------
static __device__ __forceinline__ uint32_t smem_u32(const void* p) {
    uint32_t a;
    asm("{ .reg .u64 t; cvta.to.shared.u64 t, %1; cvt.u32.u64 %0, t; }"
        : "=r"(a) : "l"(p));
    return a;
}

static __device__ __forceinline__ uint32_t sw128(uint32_t o) {
    return o ^ ((o >> 3) & 0x70u);   // SW128 swizzle for 128B rows
}

static __device__ __forceinline__ void ldsm4(uint32_t* r, uint32_t addr) {
    asm volatile("ldmatrix.sync.aligned.m8n8.x4.shared.b16 {%0,%1,%2,%3}, [%4];"
                 : "=r"(r[0]), "=r"(r[1]), "=r"(r[2]), "=r"(r[3]) : "r"(addr));
}

static __device__ __forceinline__ void mma16816(float* c, const uint32_t* a,
                                                uint32_t b0, uint32_t b1) {
    asm volatile(
        "mma.sync.aligned.m16n8k16.row.col.f32.bf16.bf16.f32 "
        "{%0,%1,%2,%3}, {%4,%5,%6,%7}, {%8,%9}, {%0,%1,%2,%3};"
        : "+f"(c[0]), "+f"(c[1]), "+f"(c[2]), "+f"(c[3])
        : "r"(a[0]), "r"(a[1]), "r"(a[2]), "r"(a[3]), "r"(b0), "r"(b1));
}

static __device__ __forceinline__ void cp_async16(uint32_t dst, const void* src) {
    asm volatile("cp.async.cg.shared.global [%0], [%1], 16;"
                 :: "r"(dst), "l"(src) : "memory");
}

// ---------------- kernel 1: normalize + positives + zero denom ----------------
// 2048 blocks x 256 threads; each half-block (128 threads) handles one row pair k.
__global__ void __launch_bounds__(256) prep_kernel(
    const float* __restrict__ ei, const float* __restrict__ ej)
{
    const int tid  = threadIdx.x;
    const int half = tid >> 7;          // 0 or 1
    const int t    = tid & 127;         // 0..127, 4 floats each
    const int k    = blockIdx.x * 2 + half;

    if (tid < 4) g_denom[blockIdx.x * 4 + tid] = 0.0f;

    const float4 a = *reinterpret_cast<const float4*>(ei + (size_t)k * DIM + t * 4);
    const float4 b = *reinterpret_cast<const float4*>(ej + (size_t)k * DIM + t * 4);

    float ni = a.x*a.x + a.y*a.y + a.z*a.z + a.w*a.w;
    float nj = b.x*b.x + b.y*b.y + b.z*b.z + b.w*b.w;
    float dd = a.x*b.x + a.y*b.y + a.z*b.z + a.w*b.w;
    #pragma unroll
    for (int o = 16; o; o >>= 1) {
        ni += __shfl_xor_sync(0xffffffffu, ni, o);
        nj += __shfl_xor_sync(0xffffffffu, nj, o);
        dd += __shfl_xor_sync(0xffffffffu, dd, o);
    }
    __shared__ float sni[2][4], snj[2][4], sdd[2][4];
    const int w2 = (tid >> 5) & 3;      // warp index within half
    if ((tid & 31) == 0) { sni[half][w2] = ni; snj[half][w2] = nj; sdd[half][w2] = dd; }
    __syncthreads();
    const float NI = sni[half][0] + sni[half][1] + sni[half][2] + sni[half][3];
    const float NJ = snj[half][0] + snj[half][1] + snj[half][2] + snj[half][3];
    const float DD = sdd[half][0] + sdd[half][1] + sdd[half][2] + sdd[half][3];

    const float rin = 1.0f / fmaxf(sqrtf(NI), 1e-12f);
    const float rjn = 1.0f / fmaxf(sqrtf(NJ), 1e-12f);

    __nv_bfloat162 ia = __floats2bfloat162_rn(a.x * rin, a.y * rin);
    __nv_bfloat162 ib = __floats2bfloat162_rn(a.z * rin, a.w * rin);
    __nv_bfloat162 ja = __floats2bfloat162_rn(b.x * rjn, b.y * rjn);
    __nv_bfloat162 jb = __floats2bfloat162_rn(b.z * rjn, b.w * rjn);
    uint2 iv, jv;
    iv.x = *reinterpret_cast<uint32_t*>(&ia); iv.y = *reinterpret_cast<uint32_t*>(&ib);
    jv.x = *reinterpret_cast<uint32_t*>(&ja); jv.y = *reinterpret_cast<uint32_t*>(&jb);
    *reinterpret_cast<uint2*>(g_reps + (size_t)k * DIM + t * 4) = iv;
    *reinterpret_cast<uint2*>(g_reps + (size_t)(BATCH + k) * DIM + t * 4) = jv;
    if (t == 0) g_pos[k] = DD * rin * rjn;
}

// ---------------- kernel 2: symmetric tiled HMMA GEMM + fused exp sums ----------------
// 256x128 tiles of sim = R R^T, enumerated over {(TM,TN): TN in [2*TM, 63]}.
// 256 threads = 8 warps in 4(M) x 2(N); warp tile 64x64. BK=64, 3-stage cp.async,
// SW128 smem, m16n8k16 bf16 HMMA. Epilogue: strictly-upper mask, exp(10*s),
// row sums -> denom[row], col sums -> denom[col].
#define GT 256
#define STG 3
#define A_BYTES 32768            // 256 rows x 64 cols bf16
#define B_BYTES 16384            // 128 rows x 64 cols bf16
#define STAGE_BYTES (A_BYTES + B_BYTES)
#define SMEM_BYTES  (STG * STAGE_BYTES + 1024)

__global__ void __launch_bounds__(GT, 1) simexp_kernel()
{
    extern __shared__ char dynsmem[];
    const uint32_t base = (smem_u32(dynsmem) + 1023u) & ~1023u;

    const int tid  = threadIdx.x;
    const int wid  = tid >> 5;
    const int lane = tid & 31;
    const int warp_m = (wid & 3) * 64;   // 4 warps over M (256)
    const int warp_n = (wid >> 2) * 64;  // 2 warps over N (128)

    // decode bid -> (TM, TN), TN in [2*TM, 63]; C(TM) = 64*TM - TM*(TM-1)
    const int bid = blockIdx.x;
    int TM = 0, C = 0;
    while (C + (NT - 2 * TM) <= bid) { C += NT - 2 * TM; ++TM; }
    const int TN = 2 * TM + (bid - C);
    const bool interior = (TN >= 2 * TM + 2);   // entire tile strictly above diagonal

    const __nv_bfloat16* Abase = g_reps + (size_t)TM * 256 * DIM;
    const __nv_bfloat16* Bbase = g_reps + (size_t)TN * 128 * DIM;

    // ---- async load of K-chunk c into stage s ----
    auto load_stage = [&](int s, int c) {
        const uint32_t As = base + (uint32_t)s * STAGE_BYTES;
        const uint32_t Bs = As + A_BYTES;
        #pragma unroll
        for (int it = 0; it < 8; ++it) {            // A: 256 rows x 8 chunks
            const int id  = tid + it * GT;           // 0..2047
            const int row = id >> 3, kc = id & 7;
            cp_async16(As + sw128((uint32_t)(row * 128 + kc * 16)),
                       Abase + (size_t)row * DIM + c * 64 + kc * 8);
        }
        #pragma unroll
        for (int it = 0; it < 4; ++it) {            // B: 128 rows x 8 chunks
            const int id  = tid + it * GT;           // 0..1023
            const int row = id >> 3, kc = id & 7;
            cp_async16(Bs + sw128((uint32_t)(row * 128 + kc * 16)),
                       Bbase + (size_t)row * DIM + c * 64 + kc * 8);
        }
    };

    float acc[4][8][4];
    #pragma unroll
    for (int mi = 0; mi < 4; ++mi)
        #pragma unroll
        for (int ni = 0; ni < 8; ++ni)
            #pragma unroll
            for (int e = 0; e < 4; ++e) acc[mi][ni][e] = 0.f;

    load_stage(0, 0);
    asm volatile("cp.async.commit_group;" ::: "memory");
    load_stage(1, 1);
    asm volatile("cp.async.commit_group;" ::: "memory");

    for (int c = 0; c < 8; ++c) {
        asm volatile("cp.async.wait_group 1;" ::: "memory");
        __syncthreads();

        if (c + 2 < 8) load_stage((c + 2) % STG, c + 2);
        asm volatile("cp.async.commit_group;" ::: "memory");

        const uint32_t As = base + (uint32_t)((c % STG) * STAGE_BYTES);
        const uint32_t Bs = As + A_BYTES;

        #pragma unroll
        for (int ks = 0; ks < 4; ++ks) {   // 4 x k16 within BK=64
            uint32_t af[4][4], bf[4][4];
            #pragma unroll
            for (int mi = 0; mi < 4; ++mi) {
                const int row = warp_m + mi * 16 + (lane & 15);
                ldsm4(af[mi], As + sw128((uint32_t)(row * 128 + ks * 32 + (lane >> 4) * 16)));
            }
            #pragma unroll
            for (int p = 0; p < 4; ++p) {
                const int row = warp_n + p * 16 + (lane & 7) + ((lane >> 4) & 1) * 8;
                ldsm4(bf[p], Bs + sw128((uint32_t)(row * 128 + ks * 32 + ((lane >> 3) & 1) * 16)));
            }
            #pragma unroll
            for (int mi = 0; mi < 4; ++mi)
                #pragma unroll
                for (int ni = 0; ni < 8; ++ni)
                    mma16816(acc[mi][ni], af[mi],
                             bf[ni >> 1][(ni & 1) * 2], bf[ni >> 1][(ni & 1) * 2 + 1]);
        }
    }

    // ---- fused epilogue: strictly-upper contributions ----
    // C-frag map: c[2h+e] = (row = lane/4 + 8h, col = 2*(lane%4) + e)
    const int growb = TM * 256 + warp_m + (lane >> 2);
    const int gcolb = TN * 128 + warp_n + 2 * (lane & 3);

    float rsum[8];                       // [mi*2 + h]
    float csum[8][2];                    // [ni][e]
    #pragma unroll
    for (int i = 0; i < 8; ++i) { rsum[i] = 0.f; csum[i][0] = 0.f; csum[i][1] = 0.f; }

    #pragma unroll
    for (int mi = 0; mi < 4; ++mi)
        #pragma unroll
        for (int ni = 0; ni < 8; ++ni)
            #pragma unroll
            for (int h = 0; h < 2; ++h)
                #pragma unroll
                for (int e = 0; e < 2; ++e) {
                    const int grow = growb + mi * 16 + h * 8;
                    const int gcol = gcolb + ni * 8 + e;
                    float v = __expf(acc[mi][ni][2 * h + e] * INV_T);
                    if (!interior && grow >= gcol) v = 0.f;  // keep strictly upper
                    rsum[mi * 2 + h] += v;
                    csum[ni][e] += v;
                }

    // row sums: reduce over lanes sharing a row (lane bits 0,1)
    #pragma unroll
    for (int i = 0; i < 8; ++i) {
        rsum[i] += __shfl_xor_sync(0xffffffffu, rsum[i], 1);
        rsum[i] += __shfl_xor_sync(0xffffffffu, rsum[i], 2);
    }
    if ((lane & 3) == 0) {
        #pragma unroll
        for (int mi = 0; mi < 4; ++mi)
            #pragma unroll
            for (int h = 0; h < 2; ++h)
                atomicAdd(&g_denom[growb + mi * 16 + h * 8], rsum[mi * 2 + h]);
    }

    // col sums: reduce over lanes sharing a column (lane bits 2,3,4)
    #pragma unroll
    for (int ni = 0; ni < 8; ++ni)
        #pragma unroll
        for (int e = 0; e < 2; ++e) {
            float v = csum[ni][e];
            v += __shfl_xor_sync(0xffffffffu, v, 4);
            v += __shfl_xor_sync(0xffffffffu, v, 8);
            v += __shfl_xor_sync(0xffffffffu, v, 16);
            if ((lane >> 2) == 0)
                atomicAdd(&g_denom[gcolb + ni * 8 + e], v);
        }
}

// ---------------- kernel 3: final reduction ----------------
__global__ void __launch_bounds__(1024) finish_kernel(float* out, int out_size)
{
    const int tid = threadIdx.x;
    float sl = 0.f, sp = 0.f;
    for (int r = tid; r < N2; r += 1024) sl += logf(g_denom[r]);
    for (int k = tid; k < BATCH; k += 1024) sp += g_pos[k];

    #pragma unroll
    for (int o = 16; o; o >>= 1) {
        sl += __shfl_xor_sync(0xffffffffu, sl, o);
        sp += __shfl_xor_sync(0xffffffffu, sp, o);
    }
    __shared__ float rl[32], rp[32];
    const int wid = tid >> 5, lid = tid & 31;
    if (lid == 0) { rl[wid] = sl; rp[wid] = sp; }
    __syncthreads();
    if (wid == 0) {
        float x = rl[lid];
        float y = rp[lid];
        #pragma unroll
        for (int o = 16; o; o >>= 1) {
            x += __shfl_xor_sync(0xffffffffu, x, o);
            y += __shfl_xor_sync(0xffffffffu, y, o);
        }
        if (lid == 0) {
            const float loss = (x - 2.0f * y * INV_T) / (float)N2;
            for (int i = 0; i < out_size; ++i) out[i] = loss;
        }
    }
}

// ---------------- launch ----------------
extern "C" void kernel_launch(void* const* d_in, const int* in_sizes, int n_in,
                              void* d_out, int out_size)
{
    (void)in_sizes; (void)n_in;
    const float* ei = (const float*)d_in[0];
    const float* ej = (const float*)d_in[1];

    cudaFuncSetAttribute(simexp_kernel,
                         cudaFuncAttributeMaxDynamicSharedMemorySize, SMEM_BYTES);

    prep_kernel<<<N2 / 4, 256>>>(ei, ej);
    simexp_kernel<<<NTILES, GT, SMEM_BYTES>>>();
    finish_kernel<<<1, 1024>>>((float*)d_out, out_size);
}